// round 9
// baseline (speedup 1.0000x reference)
#include <cuda_runtime.h>
#include <cuda_fp16.h>
#include <cstdint>

#define Bb   256
#define Nn   128
#define Dd   2048
#define DH   128
#define Mtot (Bb*Nn)   // 32768

// Scratch (device globals — no allocations allowed)
__device__ __align__(1024) __half g_wh[(size_t)DH * Dd];   // W^T fp16 [n][k], 512 KB

__device__ __forceinline__ void mma16816(float* d, const uint32_t* a, uint32_t b0, uint32_t b1) {
    asm volatile(
        "mma.sync.aligned.m16n8k16.row.col.f32.f16.f16.f32 "
        "{%0,%1,%2,%3}, {%4,%5,%6,%7}, {%8,%9}, {%0,%1,%2,%3};"
        : "+f"(d[0]), "+f"(d[1]), "+f"(d[2]), "+f"(d[3])
        : "r"(a[0]), "r"(a[1]), "r"(a[2]), "r"(a[3]), "r"(b0), "r"(b1));
}
__device__ __forceinline__ float lrelu(float s) { return s > 0.f ? s : 0.2f * s; }
__device__ __forceinline__ uint32_t packh2(float2 v) {
    __half2 h = __float22half2_rn(v);
    return *reinterpret_cast<uint32_t*>(&h);
}

// ===================== config =====================
#define KC      32
#define NTILE   (Dd / KC)            // 64
#define AROW    80                   // padded fp16 row stride (bytes), 16B-aligned, conflict-free
#define TILE16  (128 * AROW)         // 10240 B per B buffer
#define SMEMSZ  (2 * TILE16)         // 20480 B -> reg-limited 2 CTAs/SM

__global__ void __launch_bounds__(256, 2)
fused_gat(const float* __restrict__ X,
          const float* __restrict__ Wbv, const float* __restrict__ bbv,
          const float* __restrict__ Wcv, const float* __restrict__ bcv,
          const float* __restrict__ bias, float* __restrict__ out)
{
    extern __shared__ char smem[];
    const int tid = threadIdx.x;
    const int lane = tid & 31, w = tid >> 5;
    const int g = lane >> 2, tig = lane & 3;
    const int wm = w & 3;        // m-block (32 rows)
    const int wn = w >> 2;       // n-block (64 cols)

    float acc[2][8][4];
    #pragma unroll
    for (int mt = 0; mt < 2; mt++)
        #pragma unroll
        for (int nt = 0; nt < 8; nt++)
            #pragma unroll
            for (int q = 0; q < 4; q++) acc[mt][nt][q] = 0.f;

    // per-thread A base: row = b*128 + wm*32 + g, k-lane offset tig*2
    const float* xrow = X + ((size_t)blockIdx.x * 128 + wm * 32 + g) * Dd + tig * 2;
    // offsets: mt -> +16 rows (32768 floats), r&1 -> +8 rows (16384), r>>1 -> +8 k
    float2  af[2][8];       // [mt][s*4+r] fp32 pairs, tile t+1 in flight
    uint32_t a16[2][2][4];  // [mt][s][r]  converted fp16 frags, tile t
    float4  bgl[2];         // raw B tile in flight

    // ---- prologue ----
    #pragma unroll
    for (int c = 0; c < 2; c++)
        #pragma unroll
        for (int s = 0; s < 2; s++)
            #pragma unroll
            for (int r = 0; r < 4; r++)
                af[c][s * 4 + r] = __ldg(reinterpret_cast<const float2*>(
                    xrow + c * 32768 + (r & 1) * 16384 + s * 16 + (r >> 1) * 8));
    #pragma unroll
    for (int i = 0; i < 2; i++) {
        int f = tid + i * 256;
        int n = f >> 2, kq = f & 3;
        bgl[i] = *reinterpret_cast<const float4*>(
            reinterpret_cast<const char*>(g_wh) + (size_t)n * (Dd * 2) + kq * 16);
    }
    // commit B(0) to buf0
    #pragma unroll
    for (int i = 0; i < 2; i++) {
        int f = tid + i * 256;
        int n = f >> 2, kq = f & 3;
        *reinterpret_cast<float4*>(smem + (uint32_t)n * AROW + (uint32_t)kq * 16) = bgl[i];
    }
    // fetch B(1)
    #pragma unroll
    for (int i = 0; i < 2; i++) {
        int f = tid + i * 256;
        int n = f >> 2, kq = f & 3;
        bgl[i] = *reinterpret_cast<const float4*>(
            reinterpret_cast<const char*>(g_wh) + (size_t)n * (Dd * 2) + (KC * 2) + kq * 16);
    }

    #pragma unroll 1
    for (int t = 0; t < NTILE; t++) {
        __syncthreads();   // MMA(t-1) done everywhere: buf((t+1)&1) free, buf(t&1) visible

        // STS B(t+1) into the buffer MMA(t-1) just finished with
        char* bdst = smem + ((t + 1) & 1) * TILE16;
        #pragma unroll
        for (int i = 0; i < 2; i++) {
            int f = tid + i * 256;
            int n = f >> 2, kq = f & 3;
            *reinterpret_cast<float4*>(bdst + (uint32_t)n * AROW + (uint32_t)kq * 16) = bgl[i];
        }
        // LDG B(t+2)
        {
            const int tb = (t + 2 < NTILE) ? t + 2 : t;
            #pragma unroll
            for (int i = 0; i < 2; i++) {
                int f = tid + i * 256;
                int n = f >> 2, kq = f & 3;
                bgl[i] = *reinterpret_cast<const float4*>(
                    reinterpret_cast<const char*>(g_wh) + (size_t)n * (Dd * 2) +
                    (size_t)tb * (KC * 2) + kq * 16);
            }
        }
        // convert A(t) frags; then refill af with A(t+1)
        #pragma unroll
        for (int c = 0; c < 2; c++)
            #pragma unroll
            for (int s = 0; s < 2; s++)
                #pragma unroll
                for (int r = 0; r < 4; r++)
                    a16[c][s][r] = packh2(af[c][s * 4 + r]);
        {
            const int tn = (t + 1 < NTILE) ? t + 1 : t;
            const float* xt = xrow + tn * KC;
            #pragma unroll
            for (int c = 0; c < 2; c++)
                #pragma unroll
                for (int s = 0; s < 2; s++)
                    #pragma unroll
                    for (int r = 0; r < 4; r++)
                        af[c][s * 4 + r] = __ldg(reinterpret_cast<const float2*>(
                            xt + c * 32768 + (r & 1) * 16384 + s * 16 + (r >> 1) * 8));
        }

        // ---- MMA(t): B from buf(t&1), A from regs ----
        const char* bbuf = smem + (t & 1) * TILE16;
        #pragma unroll
        for (int s = 0; s < 2; s++) {
            #pragma unroll
            for (int nt = 0; nt < 8; nt++) {
                const char* nb = bbuf + (wn * 64 + nt * 8 + g) * AROW + s * 32 + tig * 4;
                uint32_t b0 = *reinterpret_cast<const uint32_t*>(nb);
                uint32_t b1 = *reinterpret_cast<const uint32_t*>(nb + 16);
                #pragma unroll
                for (int mt = 0; mt < 2; mt++)
                    mma16816(acc[mt][nt], a16[mt][s], b0, b1);
            }
        }
    }
    __syncthreads();

    // =============== fused epilogue: t1/t2, softmax(axis=i), output ===============
    float* eS1P = reinterpret_cast<float*>(smem);            // [128][2]
    float* eS2P = reinterpret_cast<float*>(smem + 1024);     // [128][2]
    float* eS1F = reinterpret_cast<float*>(smem + 2048);     // [128]
    float* eS2F = reinterpret_cast<float*>(smem + 2560);     // [128]
    float* eMX2 = reinterpret_cast<float*>(smem + 3072);     // [128][2]
    float* eZ2  = reinterpret_cast<float*>(smem + 4096);     // [128][2]
    float* eMX  = reinterpret_cast<float*>(smem + 5120);     // [128]
    float* eRZ  = reinterpret_cast<float*>(smem + 5632);     // [128]

    // (a) per-thread fragment dots with Wb/Wc
    float s1p[4] = {0.f, 0.f, 0.f, 0.f}, s2p[4] = {0.f, 0.f, 0.f, 0.f};
    #pragma unroll
    for (int nt = 0; nt < 8; nt++) {
        int c = wn * 64 + nt * 8 + 2 * tig;
        float wb0 = __ldg(Wbv + c), wb1 = __ldg(Wbv + c + 1);
        float wc0 = __ldg(Wcv + c), wc1 = __ldg(Wcv + c + 1);
        #pragma unroll
        for (int mt = 0; mt < 2; mt++) {
            s1p[mt * 2 + 0] += acc[mt][nt][0] * wb0 + acc[mt][nt][1] * wb1;
            s1p[mt * 2 + 1] += acc[mt][nt][2] * wb0 + acc[mt][nt][3] * wb1;
            s2p[mt * 2 + 0] += acc[mt][nt][0] * wc0 + acc[mt][nt][1] * wc1;
            s2p[mt * 2 + 1] += acc[mt][nt][2] * wc0 + acc[mt][nt][3] * wc1;
        }
    }
    // (b) reduce over tig
    #pragma unroll
    for (int off = 1; off <= 2; off <<= 1) {
        #pragma unroll
        for (int q = 0; q < 4; q++) {
            s1p[q] += __shfl_xor_sync(0xffffffffu, s1p[q], off);
            s2p[q] += __shfl_xor_sync(0xffffffffu, s2p[q], off);
        }
    }
    // (c) publish per-row partials per wn
    if (tig == 0) {
        #pragma unroll
        for (int q = 0; q < 4; q++) {
            int r = wm * 32 + (q >> 1) * 16 + (q & 1) * 8 + g;
            eS1P[r * 2 + wn] = s1p[q];
            eS2P[r * 2 + wn] = s2p[q];
        }
    }
    __syncthreads();
    // (d) finalize t1/t2
    if (tid < 128) {
        eS1F[tid] = eS1P[tid * 2] + eS1P[tid * 2 + 1] + bbv[0];
        eS2F[tid] = eS2P[tid * 2] + eS2P[tid * 2 + 1] + bcv[0];
    }
    __syncthreads();
    // (e) column softmax stats: 2 threads per column j
    {
        const int j = tid & 127, half = tid >> 7;
        const float s2j = eS2F[j];
        float m = -1e30f;
        #pragma unroll 4
        for (int i = half * 64; i < half * 64 + 64; i++)
            m = fmaxf(m, lrelu(eS1F[i] + s2j));
        eMX2[j * 2 + half] = m;
        __syncthreads();
        const float mj = fmaxf(eMX2[j * 2], eMX2[j * 2 + 1]);
        float z = 0.f;
        #pragma unroll 4
        for (int i = half * 64; i < half * 64 + 64; i++)
            z += __expf(lrelu(eS1F[i] + s2j) - mj);
        eZ2[j * 2 + half] = z;
        if (half == 0) eMX[j] = mj;
        __syncthreads();
        if (tid < 128) eRZ[tid] = 1.f / (eZ2[tid * 2] + eZ2[tid * 2 + 1]);
        __syncthreads();
    }
    // (f) output
    const size_t ob = (size_t)blockIdx.x * Nn * DH;
    float s1r[4];
    #pragma unroll
    for (int q = 0; q < 4; q++)
        s1r[q] = eS1F[wm * 32 + (q >> 1) * 16 + (q & 1) * 8 + g];
    #pragma unroll
    for (int nt = 0; nt < 8; nt++) {
        const int c = wn * 64 + nt * 8 + 2 * tig;
        const float s2a = eS2F[c],  s2b = eS2F[c + 1];
        const float mxa = eMX[c],   mxb = eMX[c + 1];
        const float rza = eRZ[c],   rzb = eRZ[c + 1];
        const float bia = __ldg(bias + c), bib = __ldg(bias + c + 1);
        #pragma unroll
        for (int mt = 0; mt < 2; mt++) {
            #pragma unroll
            for (int u = 0; u < 2; u++) {
                const int i = wm * 32 + mt * 16 + u * 8 + g;
                const float s1v = s1r[mt * 2 + u];
                const float ca = __expf(lrelu(s1v + s2a) - mxa) * rza;
                const float cb = __expf(lrelu(s1v + s2b) - mxb) * rzb;
                const float ha = acc[mt][nt][u * 2 + 0];
                const float hb = acc[mt][nt][u * 2 + 1];
                *reinterpret_cast<float2*>(&out[ob + (size_t)i * DH + c]) =
                    make_float2(fmaf(ca, ha, ha + bia), fmaf(cb, hb, hb + bib));
            }
        }
    }
}

// ===================== W transpose -> fp16 =====================
__global__ void wsplit_kernel(const float* __restrict__ Wa)
{
    int idx = blockIdx.x * 256 + threadIdx.x;   // [n][k]
    int n = idx >> 11, k = idx & 2047;
    g_wh[idx] = __float2half_rn(Wa[(size_t)k * DH + n]);
}

// ===================== launch =====================
extern "C" void kernel_launch(void* const* d_in, const int* in_sizes, int n_in,
                              void* d_out, int out_size)
{
    const float* X    = (const float*)d_in[0];
    const float* Wa   = (const float*)d_in[1];
    const float* Wb   = (const float*)d_in[2];
    const float* bb   = (const float*)d_in[3];
    const float* Wc   = (const float*)d_in[4];
    const float* bc   = (const float*)d_in[5];
    const float* bias = (const float*)d_in[6];
    float* out = (float*)d_out;

    wsplit_kernel<<<(Dd * DH) / 256, 256>>>(Wa);
    fused_gat<<<Bb, 256, SMEMSZ>>>(X, Wb, bb, Wc, bc, bias, out);
}

// round 10
// speedup vs baseline: 1.4837x; 1.4837x over previous
#include <cuda_runtime.h>
#include <cuda.h>
#include <cuda_fp16.h>
#include <cstdint>

#define Bb   256
#define Nn   128
#define Dd   2048
#define DH   128
#define Mtot (Bb*Nn)   // 32768

// W in MMA-fragment block layout: block(kb,nb) = 8n x 16k fp16, 256 B;
// lane l owns uint2{b0,b1} at [ (kb*16+nb)*32 + l ].  kb=k/16 (128), nb=n/8 (16).
__device__ __align__(256) uint2 g_wb[(size_t)128 * 16 * 32];   // 512 KB

// ===================== PTX helpers =====================
__device__ __forceinline__ uint32_t smem_u32(const void* p) {
    uint32_t a;
    asm("{ .reg .u64 t; cvta.to.shared.u64 t, %1; cvt.u32.u64 %0, t; }" : "=r"(a) : "l"(p));
    return a;
}
__device__ __forceinline__ void mbar_init(uint32_t m, uint32_t cnt) {
    asm volatile("mbarrier.init.shared.b64 [%0], %1;" :: "r"(m), "r"(cnt) : "memory");
}
__device__ __forceinline__ void mbar_expect_tx(uint32_t m, uint32_t bytes) {
    asm volatile("mbarrier.arrive.expect_tx.shared.b64 _, [%0], %1;" :: "r"(m), "r"(bytes) : "memory");
}
__device__ __forceinline__ void mbar_wait(uint32_t m, uint32_t ph) {
    asm volatile(
        "{\n\t.reg .pred P;\n"
        "W%=:\n\t"
        "mbarrier.try_wait.parity.acquire.cta.shared::cta.b64 P, [%0], %1, 0x989680;\n\t"
        "@P bra D%=;\n\t"
        "bra W%=;\n"
        "D%=:\n\t}"
        :: "r"(m), "r"(ph) : "memory");
}
__device__ __forceinline__ void tma2d(uint32_t dst, const CUtensorMap* map, int x, int y, uint32_t mbar) {
    asm volatile(
        "cp.async.bulk.tensor.2d.shared::cta.global.tile.mbarrier::complete_tx::bytes "
        "[%0], [%1, {%2, %3}], [%4];"
        :: "r"(dst), "l"(map), "r"(x), "r"(y), "r"(mbar) : "memory");
}
__device__ __forceinline__ void mma16816(float* d, const uint32_t* a, uint32_t b0, uint32_t b1) {
    asm volatile(
        "mma.sync.aligned.m16n8k16.row.col.f32.f16.f16.f32 "
        "{%0,%1,%2,%3}, {%4,%5,%6,%7}, {%8,%9}, {%0,%1,%2,%3};"
        : "+f"(d[0]), "+f"(d[1]), "+f"(d[2]), "+f"(d[3])
        : "r"(a[0]), "r"(a[1]), "r"(a[2]), "r"(a[3]), "r"(b0), "r"(b1));
}
__device__ __forceinline__ float lrelu(float s) { return s > 0.f ? s : 0.2f * s; }

// ===================== config =====================
#define KC        32
#define NTILE     (Dd / KC)               // 64
#define STAGES    4
#define FPA_STAGE (128 * KC * 4)          // 16384 B fp32 A tile
#define AROW      80                      // padded fp16 row stride, 16B-aligned, conflict-free
#define TILE16    (128 * AROW)            // 10240 B A fp16 tile
#define OFF_FPA   1024
#define OFF_AH    (OFF_FPA + STAGES * FPA_STAGE)   // 66560
#define SMEMSZ    (OFF_AH + TILE16)                // 76800 -> 2 CTAs/SM

__global__ void __launch_bounds__(256, 2)
fused_gat(const float* __restrict__ Wbv, const float* __restrict__ bbv,
          const float* __restrict__ Wcv, const float* __restrict__ bcv,
          const float* __restrict__ bias, float* __restrict__ out,
          const __grid_constant__ CUtensorMap mapA)
{
    extern __shared__ char smem[];
    const uint32_t sb = smem_u32(smem);
    const int tid = threadIdx.x;
    const int lane = tid & 31, w = tid >> 5;
    const int g = lane >> 2, tig = lane & 3;
    const int wm = w & 3;        // m-block (32 rows)
    const int wn = w >> 2;       // n-block (64 cols)

    if (tid == 0) {
        #pragma unroll
        for (int s = 0; s < STAGES; s++) mbar_init(sb + 8 * s, 1);
    }
    __syncthreads();
    if (tid == 0) {
        #pragma unroll
        for (int s = 0; s < STAGES; s++) {
            mbar_expect_tx(sb + 8 * s, FPA_STAGE);
            tma2d(sb + OFF_FPA + s * FPA_STAGE, &mapA, s * KC, blockIdx.x * 128, sb + 8 * s);
        }
    }

    float acc[2][8][4];
    #pragma unroll
    for (int mt = 0; mt < 2; mt++)
        #pragma unroll
        for (int nt = 0; nt < 8; nt++)
            #pragma unroll
            for (int q = 0; q < 4; q++) acc[mt][nt][q] = 0.f;

    // per-warp B base: blocks (kb*16 + wn*8 + nt), lane entry
    const uint2* wbase = g_wb + (size_t)(wn * 8) * 32 + lane;

    #pragma unroll 1
    for (int t = 0; t < NTILE; t++) {
        const int st = t & (STAGES - 1);
        const uint32_t ph = (t / STAGES) & 1;

        mbar_wait(sb + 8 * st, ph);

        // A: fp32 LDS -> cvt to fp16 in regs
        const float4* fa = reinterpret_cast<const float4*>(smem + OFF_FPA + st * FPA_STAGE);
        uint2 a16v[4];
        #pragma unroll
        for (int i = 0; i < 4; i++) {
            float4 x = fa[tid + i * 256];
            __half2 h0 = __float22half2_rn(make_float2(x.x, x.y));
            __half2 h1 = __float22half2_rn(make_float2(x.z, x.w));
            a16v[i] = make_uint2(*reinterpret_cast<uint32_t*>(&h0),
                                 *reinterpret_cast<uint32_t*>(&h1));
        }
        __syncthreads();   // all consumed stage st; MMA(t-1) done -> A buf free

        // refill the fp32 stage just consumed
        if (tid == 0 && t + STAGES < NTILE) {
            mbar_expect_tx(sb + 8 * st, FPA_STAGE);
            tma2d(sb + OFF_FPA + st * FPA_STAGE, &mapA, (t + STAGES) * KC, blockIdx.x * 128, sb + 8 * st);
        }

        // B: fragment-native LDG.64 per block (2 lines, fully coalesced); latency hides under STS/sync
        uint2 bblk[2][8];
        #pragma unroll
        for (int s = 0; s < 2; s++)
            #pragma unroll
            for (int nt = 0; nt < 8; nt++)
                bblk[s][nt] = __ldg(wbase + (size_t)((t * 2 + s) * 16 + nt) * 32);

        // commit A fp16 tile
        #pragma unroll
        for (int i = 0; i < 4; i++) {
            int f = tid + i * 256;
            int m = f >> 3, kq = f & 7;
            *reinterpret_cast<uint2*>(smem + OFF_AH + (uint32_t)m * AROW + (uint32_t)kq * 8) = a16v[i];
        }
        __syncthreads();   // A(t) visible

        // MMA: 2 k16 steps, 2m x 8n
        #pragma unroll
        for (int s = 0; s < 2; s++) {
            uint32_t ah[2][4];
            #pragma unroll
            for (int mt = 0; mt < 2; mt++) {
                const char* base = smem + OFF_AH + (wm * 32 + mt * 16 + g) * AROW + s * 32 + tig * 4;
                ah[mt][0] = *reinterpret_cast<const uint32_t*>(base);
                ah[mt][1] = *reinterpret_cast<const uint32_t*>(base + 8 * AROW);
                ah[mt][2] = *reinterpret_cast<const uint32_t*>(base + 16);
                ah[mt][3] = *reinterpret_cast<const uint32_t*>(base + 8 * AROW + 16);
            }
            #pragma unroll
            for (int nt = 0; nt < 8; nt++) {
                #pragma unroll
                for (int mt = 0; mt < 2; mt++)
                    mma16816(acc[mt][nt], ah[mt], bblk[s][nt].x, bblk[s][nt].y);
            }
        }
    }
    __syncthreads();

    // =============== fused epilogue: t1/t2, softmax(axis=i), output ===============
    float* eS1P = reinterpret_cast<float*>(smem);            // [128][2]
    float* eS2P = reinterpret_cast<float*>(smem + 1024);     // [128][2]
    float* eS1F = reinterpret_cast<float*>(smem + 2048);     // [128]
    float* eS2F = reinterpret_cast<float*>(smem + 2560);     // [128]
    float* eMX2 = reinterpret_cast<float*>(smem + 3072);     // [128][2]
    float* eZ2  = reinterpret_cast<float*>(smem + 4096);     // [128][2]
    float* eMX  = reinterpret_cast<float*>(smem + 5120);     // [128]
    float* eRZ  = reinterpret_cast<float*>(smem + 5632);     // [128]

    // (a) per-thread fragment dots with Wb/Wc
    float s1p[4] = {0.f, 0.f, 0.f, 0.f}, s2p[4] = {0.f, 0.f, 0.f, 0.f};
    #pragma unroll
    for (int nt = 0; nt < 8; nt++) {
        int c = wn * 64 + nt * 8 + 2 * tig;
        float wb0 = __ldg(Wbv + c), wb1 = __ldg(Wbv + c + 1);
        float wc0 = __ldg(Wcv + c), wc1 = __ldg(Wcv + c + 1);
        #pragma unroll
        for (int mt = 0; mt < 2; mt++) {
            s1p[mt * 2 + 0] += acc[mt][nt][0] * wb0 + acc[mt][nt][1] * wb1;
            s1p[mt * 2 + 1] += acc[mt][nt][2] * wb0 + acc[mt][nt][3] * wb1;
            s2p[mt * 2 + 0] += acc[mt][nt][0] * wc0 + acc[mt][nt][1] * wc1;
            s2p[mt * 2 + 1] += acc[mt][nt][2] * wc0 + acc[mt][nt][3] * wc1;
        }
    }
    // (b) reduce over tig
    #pragma unroll
    for (int off = 1; off <= 2; off <<= 1) {
        #pragma unroll
        for (int q = 0; q < 4; q++) {
            s1p[q] += __shfl_xor_sync(0xffffffffu, s1p[q], off);
            s2p[q] += __shfl_xor_sync(0xffffffffu, s2p[q], off);
        }
    }
    // (c) publish per-row partials per wn
    if (tig == 0) {
        #pragma unroll
        for (int q = 0; q < 4; q++) {
            int r = wm * 32 + (q >> 1) * 16 + (q & 1) * 8 + g;
            eS1P[r * 2 + wn] = s1p[q];
            eS2P[r * 2 + wn] = s2p[q];
        }
    }
    __syncthreads();
    // (d) finalize t1/t2
    if (tid < 128) {
        eS1F[tid] = eS1P[tid * 2] + eS1P[tid * 2 + 1] + bbv[0];
        eS2F[tid] = eS2P[tid * 2] + eS2P[tid * 2 + 1] + bcv[0];
    }
    __syncthreads();
    // (e) column softmax stats
    {
        const int j = tid & 127, half = tid >> 7;
        const float s2j = eS2F[j];
        float m = -1e30f;
        #pragma unroll 4
        for (int i = half * 64; i < half * 64 + 64; i++)
            m = fmaxf(m, lrelu(eS1F[i] + s2j));
        eMX2[j * 2 + half] = m;
        __syncthreads();
        const float mj = fmaxf(eMX2[j * 2], eMX2[j * 2 + 1]);
        float z = 0.f;
        #pragma unroll 4
        for (int i = half * 64; i < half * 64 + 64; i++)
            z += __expf(lrelu(eS1F[i] + s2j) - mj);
        eZ2[j * 2 + half] = z;
        if (half == 0) eMX[j] = mj;
        __syncthreads();
        if (tid < 128) eRZ[tid] = 1.f / (eZ2[tid * 2] + eZ2[tid * 2 + 1]);
        __syncthreads();
    }
    // (f) output
    const size_t ob = (size_t)blockIdx.x * Nn * DH;
    float s1r[4];
    #pragma unroll
    for (int q = 0; q < 4; q++)
        s1r[q] = eS1F[wm * 32 + (q >> 1) * 16 + (q & 1) * 8 + g];
    #pragma unroll
    for (int nt = 0; nt < 8; nt++) {
        const int c = wn * 64 + nt * 8 + 2 * tig;
        const float s2a = eS2F[c],  s2b = eS2F[c + 1];
        const float mxa = eMX[c],   mxb = eMX[c + 1];
        const float rza = eRZ[c],   rzb = eRZ[c + 1];
        const float bia = __ldg(bias + c), bib = __ldg(bias + c + 1);
        #pragma unroll
        for (int mt = 0; mt < 2; mt++) {
            #pragma unroll
            for (int u = 0; u < 2; u++) {
                const int i = wm * 32 + mt * 16 + u * 8 + g;
                const float s1v = s1r[mt * 2 + u];
                const float ca = __expf(lrelu(s1v + s2a) - mxa) * rza;
                const float cb = __expf(lrelu(s1v + s2b) - mxb) * rzb;
                const float ha = acc[mt][nt][u * 2 + 0];
                const float hb = acc[mt][nt][u * 2 + 1];
                *reinterpret_cast<float2*>(&out[ob + (size_t)i * DH + c]) =
                    make_float2(fmaf(ca, ha, ha + bia), fmaf(cb, hb, hb + bib));
            }
        }
    }
}

// ===================== W -> fragment-block layout prep =====================
// block(kb,nb): lane l: n = nb*8 + l/4, k0 = kb*16 + (l%4)*2
// b0 = half2(W[k0][n], W[k0+1][n]); b1 = half2(W[k0+8][n], W[k0+9][n])
__global__ void wb_prep(const float* __restrict__ Wa)
{
    int t = blockIdx.x * 256 + threadIdx.x;     // 0 .. 65535
    int blk = t >> 5, l = t & 31;
    int kb = blk >> 4, nb = blk & 15;
    int n  = nb * 8 + (l >> 2);
    int k0 = kb * 16 + (l & 3) * 2;
    __half2 b0 = __floats2half2_rn(Wa[(size_t)k0 * DH + n],       Wa[(size_t)(k0 + 1) * DH + n]);
    __half2 b1 = __floats2half2_rn(Wa[(size_t)(k0 + 8) * DH + n], Wa[(size_t)(k0 + 9) * DH + n]);
    g_wb[(size_t)blk * 32 + l] = make_uint2(*reinterpret_cast<uint32_t*>(&b0),
                                            *reinterpret_cast<uint32_t*>(&b1));
}

// ===================== launch =====================
typedef CUresult (*tmap_encode_t)(CUtensorMap*, CUtensorMapDataType, cuuint32_t, void*,
                                  const cuuint64_t*, const cuuint64_t*, const cuuint32_t*,
                                  const cuuint32_t*, CUtensorMapInterleave, CUtensorMapSwizzle,
                                  CUtensorMapL2promotion, CUtensorMapFloatOOBfill);

extern "C" void kernel_launch(void* const* d_in, const int* in_sizes, int n_in,
                              void* d_out, int out_size)
{
    const float* X    = (const float*)d_in[0];
    const float* Wa   = (const float*)d_in[1];
    const float* Wb   = (const float*)d_in[2];
    const float* bb   = (const float*)d_in[3];
    const float* Wc   = (const float*)d_in[4];
    const float* bc   = (const float*)d_in[5];
    const float* bias = (const float*)d_in[6];
    float* out = (float*)d_out;

    tmap_encode_t enc = nullptr;
    cudaDriverEntryPointQueryResult qr;
    cudaGetDriverEntryPointByVersion("cuTensorMapEncodeTiled", (void**)&enc, 12000,
                                     cudaEnableDefault, &qr);
    CUtensorMap mapA;
    {
        cuuint64_t dims[2]    = {Dd, Mtot};
        cuuint64_t strides[1] = {Dd * sizeof(float)};
        cuuint32_t box[2]     = {KC, 128};
        cuuint32_t es[2]      = {1, 1};
        enc(&mapA, CU_TENSOR_MAP_DATA_TYPE_FLOAT32, 2, (void*)X, dims, strides, box, es,
            CU_TENSOR_MAP_INTERLEAVE_NONE, CU_TENSOR_MAP_SWIZZLE_NONE,
            CU_TENSOR_MAP_L2_PROMOTION_L2_128B, CU_TENSOR_MAP_FLOAT_OOB_FILL_NONE);
    }

    wb_prep<<<256, 256>>>(Wa);

    cudaFuncSetAttribute(fused_gat, cudaFuncAttributeMaxDynamicSharedMemorySize, SMEMSZ);
    fused_gat<<<Bb, 256, SMEMSZ>>>(Wb, bb, Wc, bc, bias, out, mapA);
}